// round 15
// baseline (speedup 1.0000x reference)
#include <cuda_runtime.h>
#include <math.h>

#define SQ 4096
#define DMODEL 1024
#define NH 16
#define DH 64

typedef unsigned long long ull;

// Scratch (allocation-free rule: __device__ globals)
__device__ float g_q[SQ * DMODEL];
__device__ float g_k[SQ * DMODEL];
__device__ float g_v[SQ * DMODEL];
__device__ float g_attn[SQ * DMODEL];

// ---------------------------------------------------------------------------
// Packed fp32x2 helpers ("l" = b64 integer carrier)
// ---------------------------------------------------------------------------
__device__ __forceinline__ ull ffma2(ull a, ull b, ull c) {
    ull r;
    asm("fma.rn.f32x2 %0, %1, %2, %3;" : "=l"(r) : "l"(a), "l"(b), "l"(c));
    return r;
}
__device__ __forceinline__ ull pack2(float x) {
    ull r;
    asm("mov.b64 %0, {%1, %1};" : "=l"(r) : "f"(x));
    return r;
}
__device__ __forceinline__ void unpack2(ull d, float& lo, float& hi) {
    asm("mov.b64 {%0, %1}, %2;" : "=f"(lo), "=f"(hi) : "l"(d));
}

// bf16 helpers for the attention filter
// pack {lo -> bits[15:0], hi -> bits[31:16]}
__device__ __forceinline__ unsigned bf2(float lo, float hi) {
    unsigned r;
    asm("cvt.rn.bf16x2.f32 %0, %1, %2;" : "=r"(r) : "f"(hi), "f"(lo));
    return r;
}
__device__ __forceinline__ void mma_bf16(
    float& c0, float& c1, float& c2, float& c3,
    unsigned a0, unsigned a1, unsigned a2, unsigned a3,
    unsigned b0, unsigned b1)
{
    asm volatile(
        "mma.sync.aligned.m16n8k16.row.col.f32.bf16.bf16.f32 "
        "{%0,%1,%2,%3}, {%4,%5,%6,%7}, {%8,%9}, {%0,%1,%2,%3};"
        : "+f"(c0), "+f"(c1), "+f"(c2), "+f"(c3)
        : "r"(a0), "r"(a1), "r"(a2), "r"(a3), "r"(b0), "r"(b1));
}

// ---------------------------------------------------------------------------
// K1: FUSED QKV SGEMM, FFMA2, pack-free inner loop.
// A is stored DUPLICATED in smem ({a,a} per value) so the FFMA2 splat
// operand is a direct ulonglong2 LDS (broadcast-addressed, conflict-free)
// instead of 8 mov.b64 packs per kk. Per-kk budget: 6 LDS.128 + 32 FFMA2.
// k-panel 16, double-buffered smem (48KB), ONE barrier per panel (64 total),
// LDG prefetch a full panel ahead. Arithmetic bitwise-identical to R14.
// ---------------------------------------------------------------------------
#define QKV_BUF_FLOATS (16 * 256 + 16 * 128)     // Adup 16KB + Bs 8KB = 6144 fl
#define QKV_SMEM_BYTES (2 * QKV_BUF_FLOATS * 4)  // 49152 B

__global__ __launch_bounds__(256, 2) void sgemm_qkv(
    const float* __restrict__ A,
    const float* __restrict__ Wq, const float* __restrict__ Wk,
    const float* __restrict__ Wv,
    const float* __restrict__ bq, const float* __restrict__ bk,
    const float* __restrict__ bv,
    float* __restrict__ Cq, float* __restrict__ Ck, float* __restrict__ Cv)
{
    extern __shared__ float smq[];

    const int which = blockIdx.x >> 3;
    const float* __restrict__ B = (which == 0) ? Wq : (which == 1) ? Wk : Wv;
    const float* __restrict__ bias = (which == 0) ? bq : (which == 1) ? bk : bv;
    float* __restrict__ C = (which == 0) ? Cq : (which == 1) ? Ck : Cv;

    const int tid = threadIdx.x;
    const int tx = tid & 15, ty = tid >> 4;
    const int bx = (blockIdx.x & 7) * 128, by = blockIdx.y * 128;

    const int ar = tid >> 1;           // A fill: row 0..127
    const int ah = (tid & 1) * 8;      // A fill: k-offset 0 or 8
    const int brn = tid >> 4;          // B fill: panel row 0..15
    const int bc8 = (tid & 15) * 8;    // B fill: col 0..120

    ull acc2[8][4];
#pragma unroll
    for (int i = 0; i < 8; i++)
#pragma unroll
        for (int j = 0; j < 4; j++) acc2[i][j] = pack2(0.f);

    const float* Aptr = A + (size_t)(by + ar) * DMODEL + ah;
    const float* Bptr = B + (size_t)brn * DMODEL + bx + bc8;

    // ---- prologue: fill buffer 0 (panel 0)
    {
        float4 a0 = *(const float4*)(Aptr);
        float4 a1 = *(const float4*)(Aptr + 4);
        float4 b0 = *(const float4*)(Bptr);
        float4 b1 = *(const float4*)(Bptr + 4);
        float* Ad = smq;
        float* Bs = smq + 4096;
        float va[8] = {a0.x, a0.y, a0.z, a0.w, a1.x, a1.y, a1.z, a1.w};
#pragma unroll
        for (int c = 0; c < 8; c++)
            *(float2*)&Ad[(ah + c) * 256 + 2 * ar] = make_float2(va[c], va[c]);
        *(float4*)&Bs[brn * 128 + bc8] = b0;
        *(float4*)&Bs[brn * 128 + bc8 + 4] = b1;
    }
    __syncthreads();

    for (int ks = 0; ks < 64; ks++) {
        const int cur = ks & 1;
        const float* Ad = smq + cur * QKV_BUF_FLOATS;
        const float* Bs = Ad + 4096;
        const bool more = (ks + 1) < 64;

        // prefetch next panel
        float4 pa0, pa1, pb0, pb1;
        if (more) {
            const int kn = (ks + 1) * 16;
            pa0 = *(const float4*)(Aptr + kn);
            pa1 = *(const float4*)(Aptr + kn + 4);
            pb0 = *(const float4*)(Bptr + (size_t)kn * DMODEL);
            pb1 = *(const float4*)(Bptr + (size_t)kn * DMODEL + 4);
        }

#pragma unroll
        for (int kk = 0; kk < 16; kk++) {
            ulonglong2 bA = *(const ulonglong2*)&Bs[kk * 128 + 4 * tx];
            ulonglong2 bB = *(const ulonglong2*)&Bs[kk * 128 + 64 + 4 * tx];
            const float* arow = &Ad[kk * 256 + 16 * ty];
            ulonglong2 p0 = *(const ulonglong2*)&arow[0];   // rows 8ty+0,1
            ulonglong2 p1 = *(const ulonglong2*)&arow[4];   // rows 8ty+2,3
            ulonglong2 p2 = *(const ulonglong2*)&arow[8];   // rows 8ty+4,5
            ulonglong2 p3 = *(const ulonglong2*)&arow[12];  // rows 8ty+6,7
            ull aa[8] = {p0.x, p0.y, p1.x, p1.y, p2.x, p2.y, p3.x, p3.y};
#pragma unroll
            for (int i = 0; i < 8; i++) {
                acc2[i][0] = ffma2(aa[i], bA.x, acc2[i][0]);
                acc2[i][1] = ffma2(aa[i], bA.y, acc2[i][1]);
                acc2[i][2] = ffma2(aa[i], bB.x, acc2[i][2]);
                acc2[i][3] = ffma2(aa[i], bB.y, acc2[i][3]);
            }
        }

        // store prefetched panel into the other buffer
        if (more) {
            float* Adn = smq + (cur ^ 1) * QKV_BUF_FLOATS;
            float* Bsn = Adn + 4096;
            float va[8] = {pa0.x, pa0.y, pa0.z, pa0.w,
                           pa1.x, pa1.y, pa1.z, pa1.w};
#pragma unroll
            for (int c = 0; c < 8; c++)
                *(float2*)&Adn[(ah + c) * 256 + 2 * ar] =
                    make_float2(va[c], va[c]);
            *(float4*)&Bsn[brn * 128 + bc8] = pb0;
            *(float4*)&Bsn[brn * 128 + bc8 + 4] = pb1;
        }
        __syncthreads();
    }

    const int colA = bx + 4 * tx;
    const int colB = colA + 64;
    float4 biasA = *(const float4*)&bias[colA];
    float4 biasB = *(const float4*)&bias[colB];
#pragma unroll
    for (int i = 0; i < 8; i++) {
        int row = by + ty * 8 + i;
        float x0, x1, x2, x3;
        unpack2(acc2[i][0], x0, x1);
        unpack2(acc2[i][1], x2, x3);
        float4 oA = {x0 + biasA.x, x1 + biasA.y, x2 + biasA.z, x3 + biasA.w};
        unpack2(acc2[i][2], x0, x1);
        unpack2(acc2[i][3], x2, x3);
        float4 oB = {x0 + biasB.x, x1 + biasB.y, x2 + biasB.z, x3 + biasB.w};
        *(float4*)&C[(size_t)row * DMODEL + colA] = oA;
        *(float4*)&C[(size_t)row * DMODEL + colB] = oB;
    }
}

// ---------------------------------------------------------------------------
// K2: attention = bf16 TENSOR-CORE FILTER + EXACT FP32 RESCUE with
// pair-merged gating (R14-verbatim, proven: ~457us, rel_err 0.0)
// ---------------------------------------------------------------------------
#define MARGIN 0.5f
#define KPITCH_W 36
#define ATT_SMEM_BYTES (128 * 68 * 4)

__global__ __launch_bounds__(256, 2) void attn_kernel()
{
    extern __shared__ float smf[];
    unsigned* ksw = (unsigned*)smf;

    const int tid = threadIdx.x;
    const int w = tid >> 5, lane = tid & 31;
    const int g = lane >> 2, t4 = lane & 3;
    const int q0 = blockIdx.x * 128;
    const int hb = blockIdx.y * DH;
    const int R0 = q0 + w * 16 + g;
    const int R1 = R0 + 8;
    const unsigned qmask = 0xFu << (lane & 28);

    for (int it = 0; it < 8; it++) {
        int idx = tid + it * 256;
        int r = idx >> 4, d = (idx & 15) * 4;
        float4 t = *(const float4*)&g_q[(size_t)(q0 + r) * DMODEL + hb + d];
        *(float4*)&smf[r * 68 + d] = t;
    }
    __syncthreads();
    unsigned afr[4][4];
    {
        const float* q0p = &smf[(w * 16 + g) * 68];
        const float* q1p = q0p + 8 * 68;
#pragma unroll
        for (int s = 0; s < 4; s++) {
            int kb = 16 * s + 2 * t4;
            afr[s][0] = bf2(q0p[kb], q0p[kb + 1]);
            afr[s][1] = bf2(q1p[kb], q1p[kb + 1]);
            afr[s][2] = bf2(q0p[kb + 8], q0p[kb + 9]);
            afr[s][3] = bf2(q1p[kb + 8], q1p[kb + 9]);
        }
    }

    float run0 = INFINITY, run1 = INFINITY;
    float rmax0 = -INFINITY, rmax1 = -INFINITY;
    float rsum0 = 0.f, rsum1 = 0.f;
    float acc0[16], acc1[16];
#pragma unroll
    for (int d = 0; d < 16; d++) { acc0[d] = 0.f; acc1[d] = 0.f; }

    const int A0 = q0 + w * 16;
    for (int k0 = 0; k0 < SQ; k0 += 128) {
        __syncthreads();
        for (int it = 0; it < 8; it++) {
            int idx = tid + it * 256;
            int r = idx >> 4, d = (idx & 15) * 4;
            float4 t = *(const float4*)&g_k[(size_t)(k0 + r) * DMODEL + hb + d];
            int w0 = d >> 1, w1 = w0 + 1;
            ksw[r * KPITCH_W + ((w0 & 3) * 8 + (w0 >> 2))] = bf2(t.x, t.y);
            ksw[r * KPITCH_W + ((w1 & 3) * 8 + (w1 >> 2))] = bf2(t.z, t.w);
        }
        __syncthreads();

        const bool careful = (k0 <= A0 + 15) && (k0 + 127 >= A0 - 1);

#pragma unroll 1
        for (int tp = 0; tp < 8; tp++) {
            const int tA = 2 * tp, tB = 2 * tp + 1;
            const uint4* kfA = (const uint4*)&ksw[(tA * 8 + g) * KPITCH_W + t4 * 8];
            uint4 uA0 = kfA[0];
            uint4 uA1 = kfA[1];
            float a0 = 0.f, a1 = 0.f, a2 = 0.f, a3 = 0.f;
            mma_bf16(a0, a1, a2, a3,
                     afr[0][0], afr[0][1], afr[0][2], afr[0][3], uA0.x, uA0.y);
            mma_bf16(a0, a1, a2, a3,
                     afr[1][0], afr[1][1], afr[1][2], afr[1][3], uA0.z, uA0.w);
            mma_bf16(a0, a1, a2, a3,
                     afr[2][0], afr[2][1], afr[2][2], afr[2][3], uA1.x, uA1.y);
            mma_bf16(a0, a1, a2, a3,
                     afr[3][0], afr[3][1], afr[3][2], afr[3][3], uA1.z, uA1.w);
            const uint4* kfB = (const uint4*)&ksw[(tB * 8 + g) * KPITCH_W + t4 * 8];
            uint4 uB0 = kfB[0];
            uint4 uB1 = kfB[1];
            float b0 = 0.f, b1 = 0.f, b2 = 0.f, b3 = 0.f;
            mma_bf16(b0, b1, b2, b3,
                     afr[0][0], afr[0][1], afr[0][2], afr[0][3], uB0.x, uB0.y);
            mma_bf16(b0, b1, b2, b3,
                     afr[1][0], afr[1][1], afr[1][2], afr[1][3], uB0.z, uB0.w);
            mma_bf16(b0, b1, b2, b3,
                     afr[2][0], afr[2][1], afr[2][2], afr[2][3], uB1.x, uB1.y);
            mma_bf16(b0, b1, b2, b3,
                     afr[3][0], afr[3][1], afr[3][2], afr[3][3], uB1.z, uB1.w);

            const int jA = k0 + 8 * tA + 2 * t4;
            const int jB = k0 + 8 * tB + 2 * t4;
            if (careful) {
                if (jA == R0 || jA == R0 - 1) a0 = INFINITY;
                if (jA + 1 == R0 || jA + 1 == R0 - 1) a1 = INFINITY;
                if (jA == R1 || jA == R1 - 1) a2 = INFINITY;
                if (jA + 1 == R1 || jA + 1 == R1 - 1) a3 = INFINITY;
                if (jB == R0 || jB == R0 - 1) b0 = INFINITY;
                if (jB + 1 == R0 || jB + 1 == R0 - 1) b1 = INFINITY;
                if (jB == R1 || jB == R1 - 1) b2 = INFINITY;
                if (jB + 1 == R1 || jB + 1 == R1 - 1) b3 = INFINITY;
            }
            float m0 = fminf(fminf(a0, a1), fminf(b0, b1));
            float m1 = fminf(fminf(a2, a3), fminf(b2, b3));
            run0 = fminf(run0, m0);
            run1 = fminf(run1, m1);
            bool fl = (m0 <= run0 + MARGIN) || (m1 <= run1 + MARGIN);

            if (__any_sync(0xffffffffu, fl)) {
                const float th0 = run0 + MARGIN;
                const float th1 = run1 + MARGIN;
                unsigned bal[8];
                bal[0] = __ballot_sync(0xffffffffu, a0 <= th0);
                bal[1] = __ballot_sync(0xffffffffu, a1 <= th0);
                bal[2] = __ballot_sync(0xffffffffu, a2 <= th1);
                bal[3] = __ballot_sync(0xffffffffu, a3 <= th1);
                bal[4] = __ballot_sync(0xffffffffu, b0 <= th0);
                bal[5] = __ballot_sync(0xffffffffu, b1 <= th0);
                bal[6] = __ballot_sync(0xffffffffu, b2 <= th1);
                bal[7] = __ballot_sync(0xffffffffu, b3 <= th1);
#pragma unroll
                for (int e = 0; e < 8; e++) {
                    unsigned qb = (bal[e] >> (lane & 28)) & 0xFu;
                    const int i = ((e & 3) >= 2) ? R1 : R0;
                    const int tt = (e < 4) ? tA : tB;
                    while (qb) {
                        int b = __ffs((int)qb) - 1;
                        qb &= qb - 1;
                        int j = k0 + 8 * tt + 2 * b + (e & 1);
                        const float* qg = &g_q[(size_t)i * DMODEL + hb + t4 * 16];
                        const float* kg = &g_k[(size_t)j * DMODEL + hb + t4 * 16];
                        float s = 0.f;
#pragma unroll
                        for (int c4 = 0; c4 < 4; c4++) {
                            float4 qv = *(const float4*)&qg[c4 * 4];
                            float4 kv = *(const float4*)&kg[c4 * 4];
                            s = fmaf(qv.x, kv.x, s);
                            s = fmaf(qv.y, kv.y, s);
                            s = fmaf(qv.z, kv.z, s);
                            s = fmaf(qv.w, kv.w, s);
                        }
                        s += __shfl_xor_sync(qmask, s, 1);
                        s += __shfl_xor_sync(qmask, s, 2);
                        float y = s * 0.125f;
                        if (!(j == i || j == i - 1)) y = y * -1000000000.0f;
                        const float* vg = &g_v[(size_t)j * DMODEL + hb + t4 * 16];
                        if ((e & 3) < 2) {
                            if (y > rmax0) {
                                float scl = expf(rmax0 - y);
                                rsum0 *= scl;
#pragma unroll
                                for (int d = 0; d < 16; d++) acc0[d] *= scl;
                                rmax0 = y;
                            }
                            float p = expf(y - rmax0);
                            rsum0 += p;
#pragma unroll
                            for (int c4 = 0; c4 < 4; c4++) {
                                float4 vv = *(const float4*)&vg[c4 * 4];
                                acc0[c4 * 4 + 0] = fmaf(p, vv.x, acc0[c4 * 4 + 0]);
                                acc0[c4 * 4 + 1] = fmaf(p, vv.y, acc0[c4 * 4 + 1]);
                                acc0[c4 * 4 + 2] = fmaf(p, vv.z, acc0[c4 * 4 + 2]);
                                acc0[c4 * 4 + 3] = fmaf(p, vv.w, acc0[c4 * 4 + 3]);
                            }
                        } else {
                            if (y > rmax1) {
                                float scl = expf(rmax1 - y);
                                rsum1 *= scl;
#pragma unroll
                                for (int d = 0; d < 16; d++) acc1[d] *= scl;
                                rmax1 = y;
                            }
                            float p = expf(y - rmax1);
                            rsum1 += p;
#pragma unroll
                            for (int c4 = 0; c4 < 4; c4++) {
                                float4 vv = *(const float4*)&vg[c4 * 4];
                                acc1[c4 * 4 + 0] = fmaf(p, vv.x, acc1[c4 * 4 + 0]);
                                acc1[c4 * 4 + 1] = fmaf(p, vv.y, acc1[c4 * 4 + 1]);
                                acc1[c4 * 4 + 2] = fmaf(p, vv.z, acc1[c4 * 4 + 2]);
                                acc1[c4 * 4 + 3] = fmaf(p, vv.w, acc1[c4 * 4 + 3]);
                            }
                        }
                    }
                }
            }
        }
        run0 = fminf(run0, __shfl_xor_sync(0xffffffffu, run0, 1));
        run0 = fminf(run0, __shfl_xor_sync(0xffffffffu, run0, 2));
        run1 = fminf(run1, __shfl_xor_sync(0xffffffffu, run1, 1));
        run1 = fminf(run1, __shfl_xor_sync(0xffffffffu, run1, 2));
    }

    {
        float inv0 = 1.f / rsum0;
        float inv1 = 1.f / rsum1;
        float* o0 = &g_attn[(size_t)R0 * DMODEL + hb + t4 * 16];
        float* o1 = &g_attn[(size_t)R1 * DMODEL + hb + t4 * 16];
#pragma unroll
        for (int c4 = 0; c4 < 4; c4++) {
            float4 a = {acc0[c4 * 4 + 0] * inv0, acc0[c4 * 4 + 1] * inv0,
                        acc0[c4 * 4 + 2] * inv0, acc0[c4 * 4 + 3] * inv0};
            float4 b = {acc1[c4 * 4 + 0] * inv1, acc1[c4 * 4 + 1] * inv1,
                        acc1[c4 * 4 + 2] * inv1, acc1[c4 * 4 + 3] * inv1};
            *(float4*)&o0[c4 * 4] = a;
            *(float4*)&o1[c4 * 4] = b;
        }
    }
}

// ---------------------------------------------------------------------------
// K3: out[4096,64] = g_attn[4096,1024] @ Wm[1024,64] + bm  (verbatim)
// ---------------------------------------------------------------------------
__global__ __launch_bounds__(256) void sgemm_out(
    const float* __restrict__ A, const float* __restrict__ B,
    const float* __restrict__ bias, float* __restrict__ C)
{
    __shared__ float As[16][64];
    __shared__ float Bs[16][64];

    const int tid = threadIdx.x;
    const int tx = tid & 15, ty = tid >> 4;
    const int by = blockIdx.x * 64;

    const int ar = tid >> 2;
    const int ac = (tid & 3) * 4;
    const int br = tid >> 4;
    const int bc = (tid & 15) * 4;

    float acc[4][4];
#pragma unroll
    for (int i = 0; i < 4; i++)
#pragma unroll
        for (int j = 0; j < 4; j++) acc[i][j] = 0.f;

    for (int k0 = 0; k0 < DMODEL; k0 += 16) {
        float4 av = *(const float4*)&A[(size_t)(by + ar) * DMODEL + k0 + ac];
        float4 bv = *(const float4*)&B[(size_t)(k0 + br) * 64 + bc];
        As[ac + 0][ar] = av.x;
        As[ac + 1][ar] = av.y;
        As[ac + 2][ar] = av.z;
        As[ac + 3][ar] = av.w;
        *(float4*)&Bs[br][bc] = bv;
        __syncthreads();
#pragma unroll
        for (int kk = 0; kk < 16; kk++) {
            float4 a = *(const float4*)&As[kk][ty * 4];
            float4 b = *(const float4*)&Bs[kk][tx * 4];
            float av4[4] = {a.x, a.y, a.z, a.w};
            float bv4[4] = {b.x, b.y, b.z, b.w};
#pragma unroll
            for (int i = 0; i < 4; i++)
#pragma unroll
                for (int j = 0; j < 4; j++)
                    acc[i][j] = fmaf(av4[i], bv4[j], acc[i][j]);
        }
        __syncthreads();
    }

#pragma unroll
    for (int i = 0; i < 4; i++) {
        int row = by + ty * 4 + i;
        float4 o;
        o.x = acc[i][0] + bias[tx * 4 + 0];
        o.y = acc[i][1] + bias[tx * 4 + 1];
        o.z = acc[i][2] + bias[tx * 4 + 2];
        o.w = acc[i][3] + bias[tx * 4 + 3];
        *(float4*)&C[(size_t)row * 64 + tx * 4] = o;
    }
}

// ---------------------------------------------------------------------------
// kernel_launch
// ---------------------------------------------------------------------------
extern "C" void kernel_launch(void* const* d_in, const int* in_sizes, int n_in,
                              void* d_out, int out_size)
{
    const float* X  = (const float*)d_in[0];
    const float* Wq = (const float*)d_in[2];
    const float* bq = (const float*)d_in[3];
    const float* Wk = (const float*)d_in[4];
    const float* bk = (const float*)d_in[5];
    const float* Wv = (const float*)d_in[6];
    const float* bv = (const float*)d_in[7];
    const float* Wm = (const float*)d_in[8];
    const float* bm = (const float*)d_in[9];
    float* out = (float*)d_out;

    float *qp, *kp, *vp, *ap;
    cudaGetSymbolAddress((void**)&qp, g_q);
    cudaGetSymbolAddress((void**)&kp, g_k);
    cudaGetSymbolAddress((void**)&vp, g_v);
    cudaGetSymbolAddress((void**)&ap, g_attn);

    cudaFuncSetAttribute(sgemm_qkv,
                         cudaFuncAttributeMaxDynamicSharedMemorySize,
                         QKV_SMEM_BYTES);
    sgemm_qkv<<<dim3(24, 32), 256, QKV_SMEM_BYTES>>>(
        X, Wq, Wk, Wv, bq, bk, bv, qp, kp, vp);

    cudaFuncSetAttribute(attn_kernel,
                         cudaFuncAttributeMaxDynamicSharedMemorySize,
                         ATT_SMEM_BYTES);
    attn_kernel<<<dim3(SQ / 128, NH), 256, ATT_SMEM_BYTES>>>();

    sgemm_out<<<SQ / 64, 256>>>(ap, Wm, bm, out);
}

// round 16
// speedup vs baseline: 1.1283x; 1.1283x over previous
#include <cuda_runtime.h>
#include <math.h>

#define SQ 4096
#define DMODEL 1024
#define NH 16
#define DH 64

typedef unsigned long long ull;

// Scratch (allocation-free rule: __device__ globals)
__device__ float g_q[SQ * DMODEL];
__device__ float g_k[SQ * DMODEL];
__device__ float g_v[SQ * DMODEL];
__device__ float g_attn[SQ * DMODEL];

// ---------------------------------------------------------------------------
// Packed fp32x2 helpers ("l" = b64 integer carrier)
// ---------------------------------------------------------------------------
__device__ __forceinline__ ull ffma2(ull a, ull b, ull c) {
    ull r;
    asm("fma.rn.f32x2 %0, %1, %2, %3;" : "=l"(r) : "l"(a), "l"(b), "l"(c));
    return r;
}
__device__ __forceinline__ ull pack2(float x) {
    ull r;
    asm("mov.b64 %0, {%1, %1};" : "=l"(r) : "f"(x));
    return r;
}
__device__ __forceinline__ void unpack2(ull d, float& lo, float& hi) {
    asm("mov.b64 {%0, %1}, %2;" : "=f"(lo), "=f"(hi) : "l"(d));
}

// bf16 helpers for the attention filter
// pack {lo -> bits[15:0], hi -> bits[31:16]}
__device__ __forceinline__ unsigned bf2(float lo, float hi) {
    unsigned r;
    asm("cvt.rn.bf16x2.f32 %0, %1, %2;" : "=r"(r) : "f"(hi), "f"(lo));
    return r;
}
__device__ __forceinline__ void mma_bf16(
    float& c0, float& c1, float& c2, float& c3,
    unsigned a0, unsigned a1, unsigned a2, unsigned a3,
    unsigned b0, unsigned b1)
{
    asm volatile(
        "mma.sync.aligned.m16n8k16.row.col.f32.bf16.bf16.f32 "
        "{%0,%1,%2,%3}, {%4,%5,%6,%7}, {%8,%9}, {%0,%1,%2,%3};"
        : "+f"(c0), "+f"(c1), "+f"(c2), "+f"(c3)
        : "r"(a0), "r"(a1), "r"(a2), "r"(a3), "r"(b0), "r"(b1));
}

// ---------------------------------------------------------------------------
// K1: FUSED QKV SGEMM — R14 inner loop (4 LDS.128 + 8 packs + 32 FFMA2/kk,
// measured 62.8% fma), restructured: k-panel 16, double-buffered smem
// (2 x 16KB), ONE barrier per panel (64 vs 256), A prefetched a full panel
// ahead (~700cyc compute covers DRAM), B prefetched mid-panel (covers L2).
// NO A-duplication (R15 proved that trade loses to smem bandwidth).
// k-order preserved -> output bitwise identical to R14.
// ---------------------------------------------------------------------------
#define QKV_BUF_FLOATS 4096                      // As 16x128 + Bs 16x128
#define QKV_SMEM_BYTES (2 * QKV_BUF_FLOATS * 4)  // 32768 B

__global__ __launch_bounds__(256, 2) void sgemm_qkv(
    const float* __restrict__ A,
    const float* __restrict__ Wq, const float* __restrict__ Wk,
    const float* __restrict__ Wv,
    const float* __restrict__ bq, const float* __restrict__ bk,
    const float* __restrict__ bv,
    float* __restrict__ Cq, float* __restrict__ Ck, float* __restrict__ Cv)
{
    extern __shared__ float smq[];

    const int which = blockIdx.x >> 3;
    const float* __restrict__ B = (which == 0) ? Wq : (which == 1) ? Wk : Wv;
    const float* __restrict__ bias = (which == 0) ? bq : (which == 1) ? bk : bv;
    float* __restrict__ C = (which == 0) ? Cq : (which == 1) ? Ck : Cv;

    const int tid = threadIdx.x;
    const int tx = tid & 15, ty = tid >> 4;
    const int bx = (blockIdx.x & 7) * 128, by = blockIdx.y * 128;

    const int ar = tid >> 1;           // A fill: row 0..127
    const int ah = (tid & 1) * 8;      // A fill: k-offset 0 or 8
    const int brn = tid >> 4;          // B fill: panel row 0..15
    const int bc8 = (tid & 15) * 8;    // B fill: col 0..120

    ull acc2[8][4];
#pragma unroll
    for (int i = 0; i < 8; i++)
#pragma unroll
        for (int j = 0; j < 4; j++) acc2[i][j] = pack2(0.f);

    const float* Aptr = A + (size_t)(by + ar) * DMODEL + ah;
    const float* Bptr = B + (size_t)brn * DMODEL + bx + bc8;

    // ---- prologue: fill buffer 0 (panel 0)
    {
        float4 a0 = *(const float4*)(Aptr);
        float4 a1 = *(const float4*)(Aptr + 4);
        float4 b0 = *(const float4*)(Bptr);
        float4 b1 = *(const float4*)(Bptr + 4);
        float* As = smq;
        float* Bs = smq + 2048;
        As[(ah + 0) * 128 + ar] = a0.x;
        As[(ah + 1) * 128 + ar] = a0.y;
        As[(ah + 2) * 128 + ar] = a0.z;
        As[(ah + 3) * 128 + ar] = a0.w;
        As[(ah + 4) * 128 + ar] = a1.x;
        As[(ah + 5) * 128 + ar] = a1.y;
        As[(ah + 6) * 128 + ar] = a1.z;
        As[(ah + 7) * 128 + ar] = a1.w;
        *(float4*)&Bs[brn * 128 + bc8] = b0;
        *(float4*)&Bs[brn * 128 + bc8 + 4] = b1;
    }
    __syncthreads();

    for (int ks = 0; ks < 64; ks++) {
        const int cur = ks & 1;
        const float* As = smq + cur * QKV_BUF_FLOATS;
        const float* Bs = As + 2048;
        const bool more = (ks + 1) < 64;

        // A prefetch for next panel (held over full panel, covers DRAM)
        float4 pa0, pa1;
        if (more) {
            const int kn = (ks + 1) * 16;
            pa0 = *(const float4*)(Aptr + kn);
            pa1 = *(const float4*)(Aptr + kn + 4);
        }

#pragma unroll
        for (int kk = 0; kk < 8; kk++) {
            ulonglong2 bA = *(const ulonglong2*)&Bs[kk * 128 + 4 * tx];
            ulonglong2 bB = *(const ulonglong2*)&Bs[kk * 128 + 64 + 4 * tx];
            float4 a0 = *(const float4*)&As[kk * 128 + ty * 8];
            float4 a1 = *(const float4*)&As[kk * 128 + ty * 8 + 4];
            float aa[8] = {a0.x, a0.y, a0.z, a0.w, a1.x, a1.y, a1.z, a1.w};
#pragma unroll
            for (int i = 0; i < 8; i++) {
                ull a2 = pack2(aa[i]);
                acc2[i][0] = ffma2(a2, bA.x, acc2[i][0]);
                acc2[i][1] = ffma2(a2, bA.y, acc2[i][1]);
                acc2[i][2] = ffma2(a2, bB.x, acc2[i][2]);
                acc2[i][3] = ffma2(a2, bB.y, acc2[i][3]);
            }
        }

        // B prefetch mid-panel (held ~8 kk, covers L2 latency)
        float4 pb0, pb1;
        if (more) {
            const int kn = (ks + 1) * 16;
            pb0 = *(const float4*)(Bptr + (size_t)kn * DMODEL);
            pb1 = *(const float4*)(Bptr + (size_t)kn * DMODEL + 4);
        }

#pragma unroll
        for (int kk = 8; kk < 16; kk++) {
            ulonglong2 bA = *(const ulonglong2*)&Bs[kk * 128 + 4 * tx];
            ulonglong2 bB = *(const ulonglong2*)&Bs[kk * 128 + 64 + 4 * tx];
            float4 a0 = *(const float4*)&As[kk * 128 + ty * 8];
            float4 a1 = *(const float4*)&As[kk * 128 + ty * 8 + 4];
            float aa[8] = {a0.x, a0.y, a0.z, a0.w, a1.x, a1.y, a1.z, a1.w};
#pragma unroll
            for (int i = 0; i < 8; i++) {
                ull a2 = pack2(aa[i]);
                acc2[i][0] = ffma2(a2, bA.x, acc2[i][0]);
                acc2[i][1] = ffma2(a2, bA.y, acc2[i][1]);
                acc2[i][2] = ffma2(a2, bB.x, acc2[i][2]);
                acc2[i][3] = ffma2(a2, bB.y, acc2[i][3]);
            }
        }

        // store prefetched panel into the other buffer, single barrier
        if (more) {
            float* Asn = smq + (cur ^ 1) * QKV_BUF_FLOATS;
            float* Bsn = Asn + 2048;
            Asn[(ah + 0) * 128 + ar] = pa0.x;
            Asn[(ah + 1) * 128 + ar] = pa0.y;
            Asn[(ah + 2) * 128 + ar] = pa0.z;
            Asn[(ah + 3) * 128 + ar] = pa0.w;
            Asn[(ah + 4) * 128 + ar] = pa1.x;
            Asn[(ah + 5) * 128 + ar] = pa1.y;
            Asn[(ah + 6) * 128 + ar] = pa1.z;
            Asn[(ah + 7) * 128 + ar] = pa1.w;
            *(float4*)&Bsn[brn * 128 + bc8] = pb0;
            *(float4*)&Bsn[brn * 128 + bc8 + 4] = pb1;
        }
        __syncthreads();
    }

    const int colA = bx + 4 * tx;
    const int colB = colA + 64;
    float4 biasA = *(const float4*)&bias[colA];
    float4 biasB = *(const float4*)&bias[colB];
#pragma unroll
    for (int i = 0; i < 8; i++) {
        int row = by + ty * 8 + i;
        float x0, x1, x2, x3;
        unpack2(acc2[i][0], x0, x1);
        unpack2(acc2[i][1], x2, x3);
        float4 oA = {x0 + biasA.x, x1 + biasA.y, x2 + biasA.z, x3 + biasA.w};
        unpack2(acc2[i][2], x0, x1);
        unpack2(acc2[i][3], x2, x3);
        float4 oB = {x0 + biasB.x, x1 + biasB.y, x2 + biasB.z, x3 + biasB.w};
        *(float4*)&C[(size_t)row * DMODEL + colA] = oA;
        *(float4*)&C[(size_t)row * DMODEL + colB] = oB;
    }
}

// ---------------------------------------------------------------------------
// K2: attention = bf16 TENSOR-CORE FILTER + EXACT FP32 RESCUE with
// pair-merged gating (R14-verbatim, proven: ~457us, rel_err 0.0)
// ---------------------------------------------------------------------------
#define MARGIN 0.5f
#define KPITCH_W 36
#define ATT_SMEM_BYTES (128 * 68 * 4)

__global__ __launch_bounds__(256, 2) void attn_kernel()
{
    extern __shared__ float smf[];
    unsigned* ksw = (unsigned*)smf;

    const int tid = threadIdx.x;
    const int w = tid >> 5, lane = tid & 31;
    const int g = lane >> 2, t4 = lane & 3;
    const int q0 = blockIdx.x * 128;
    const int hb = blockIdx.y * DH;
    const int R0 = q0 + w * 16 + g;
    const int R1 = R0 + 8;
    const unsigned qmask = 0xFu << (lane & 28);

    for (int it = 0; it < 8; it++) {
        int idx = tid + it * 256;
        int r = idx >> 4, d = (idx & 15) * 4;
        float4 t = *(const float4*)&g_q[(size_t)(q0 + r) * DMODEL + hb + d];
        *(float4*)&smf[r * 68 + d] = t;
    }
    __syncthreads();
    unsigned afr[4][4];
    {
        const float* q0p = &smf[(w * 16 + g) * 68];
        const float* q1p = q0p + 8 * 68;
#pragma unroll
        for (int s = 0; s < 4; s++) {
            int kb = 16 * s + 2 * t4;
            afr[s][0] = bf2(q0p[kb], q0p[kb + 1]);
            afr[s][1] = bf2(q1p[kb], q1p[kb + 1]);
            afr[s][2] = bf2(q0p[kb + 8], q0p[kb + 9]);
            afr[s][3] = bf2(q1p[kb + 8], q1p[kb + 9]);
        }
    }

    float run0 = INFINITY, run1 = INFINITY;
    float rmax0 = -INFINITY, rmax1 = -INFINITY;
    float rsum0 = 0.f, rsum1 = 0.f;
    float acc0[16], acc1[16];
#pragma unroll
    for (int d = 0; d < 16; d++) { acc0[d] = 0.f; acc1[d] = 0.f; }

    const int A0 = q0 + w * 16;
    for (int k0 = 0; k0 < SQ; k0 += 128) {
        __syncthreads();
        for (int it = 0; it < 8; it++) {
            int idx = tid + it * 256;
            int r = idx >> 4, d = (idx & 15) * 4;
            float4 t = *(const float4*)&g_k[(size_t)(k0 + r) * DMODEL + hb + d];
            int w0 = d >> 1, w1 = w0 + 1;
            ksw[r * KPITCH_W + ((w0 & 3) * 8 + (w0 >> 2))] = bf2(t.x, t.y);
            ksw[r * KPITCH_W + ((w1 & 3) * 8 + (w1 >> 2))] = bf2(t.z, t.w);
        }
        __syncthreads();

        const bool careful = (k0 <= A0 + 15) && (k0 + 127 >= A0 - 1);

#pragma unroll 1
        for (int tp = 0; tp < 8; tp++) {
            const int tA = 2 * tp, tB = 2 * tp + 1;
            const uint4* kfA = (const uint4*)&ksw[(tA * 8 + g) * KPITCH_W + t4 * 8];
            uint4 uA0 = kfA[0];
            uint4 uA1 = kfA[1];
            float a0 = 0.f, a1 = 0.f, a2 = 0.f, a3 = 0.f;
            mma_bf16(a0, a1, a2, a3,
                     afr[0][0], afr[0][1], afr[0][2], afr[0][3], uA0.x, uA0.y);
            mma_bf16(a0, a1, a2, a3,
                     afr[1][0], afr[1][1], afr[1][2], afr[1][3], uA0.z, uA0.w);
            mma_bf16(a0, a1, a2, a3,
                     afr[2][0], afr[2][1], afr[2][2], afr[2][3], uA1.x, uA1.y);
            mma_bf16(a0, a1, a2, a3,
                     afr[3][0], afr[3][1], afr[3][2], afr[3][3], uA1.z, uA1.w);
            const uint4* kfB = (const uint4*)&ksw[(tB * 8 + g) * KPITCH_W + t4 * 8];
            uint4 uB0 = kfB[0];
            uint4 uB1 = kfB[1];
            float b0 = 0.f, b1 = 0.f, b2 = 0.f, b3 = 0.f;
            mma_bf16(b0, b1, b2, b3,
                     afr[0][0], afr[0][1], afr[0][2], afr[0][3], uB0.x, uB0.y);
            mma_bf16(b0, b1, b2, b3,
                     afr[1][0], afr[1][1], afr[1][2], afr[1][3], uB0.z, uB0.w);
            mma_bf16(b0, b1, b2, b3,
                     afr[2][0], afr[2][1], afr[2][2], afr[2][3], uB1.x, uB1.y);
            mma_bf16(b0, b1, b2, b3,
                     afr[3][0], afr[3][1], afr[3][2], afr[3][3], uB1.z, uB1.w);

            const int jA = k0 + 8 * tA + 2 * t4;
            const int jB = k0 + 8 * tB + 2 * t4;
            if (careful) {
                if (jA == R0 || jA == R0 - 1) a0 = INFINITY;
                if (jA + 1 == R0 || jA + 1 == R0 - 1) a1 = INFINITY;
                if (jA == R1 || jA == R1 - 1) a2 = INFINITY;
                if (jA + 1 == R1 || jA + 1 == R1 - 1) a3 = INFINITY;
                if (jB == R0 || jB == R0 - 1) b0 = INFINITY;
                if (jB + 1 == R0 || jB + 1 == R0 - 1) b1 = INFINITY;
                if (jB == R1 || jB == R1 - 1) b2 = INFINITY;
                if (jB + 1 == R1 || jB + 1 == R1 - 1) b3 = INFINITY;
            }
            float m0 = fminf(fminf(a0, a1), fminf(b0, b1));
            float m1 = fminf(fminf(a2, a3), fminf(b2, b3));
            run0 = fminf(run0, m0);
            run1 = fminf(run1, m1);
            bool fl = (m0 <= run0 + MARGIN) || (m1 <= run1 + MARGIN);

            if (__any_sync(0xffffffffu, fl)) {
                const float th0 = run0 + MARGIN;
                const float th1 = run1 + MARGIN;
                unsigned bal[8];
                bal[0] = __ballot_sync(0xffffffffu, a0 <= th0);
                bal[1] = __ballot_sync(0xffffffffu, a1 <= th0);
                bal[2] = __ballot_sync(0xffffffffu, a2 <= th1);
                bal[3] = __ballot_sync(0xffffffffu, a3 <= th1);
                bal[4] = __ballot_sync(0xffffffffu, b0 <= th0);
                bal[5] = __ballot_sync(0xffffffffu, b1 <= th0);
                bal[6] = __ballot_sync(0xffffffffu, b2 <= th1);
                bal[7] = __ballot_sync(0xffffffffu, b3 <= th1);
#pragma unroll
                for (int e = 0; e < 8; e++) {
                    unsigned qb = (bal[e] >> (lane & 28)) & 0xFu;
                    const int i = ((e & 3) >= 2) ? R1 : R0;
                    const int tt = (e < 4) ? tA : tB;
                    while (qb) {
                        int b = __ffs((int)qb) - 1;
                        qb &= qb - 1;
                        int j = k0 + 8 * tt + 2 * b + (e & 1);
                        const float* qg = &g_q[(size_t)i * DMODEL + hb + t4 * 16];
                        const float* kg = &g_k[(size_t)j * DMODEL + hb + t4 * 16];
                        float s = 0.f;
#pragma unroll
                        for (int c4 = 0; c4 < 4; c4++) {
                            float4 qv = *(const float4*)&qg[c4 * 4];
                            float4 kv = *(const float4*)&kg[c4 * 4];
                            s = fmaf(qv.x, kv.x, s);
                            s = fmaf(qv.y, kv.y, s);
                            s = fmaf(qv.z, kv.z, s);
                            s = fmaf(qv.w, kv.w, s);
                        }
                        s += __shfl_xor_sync(qmask, s, 1);
                        s += __shfl_xor_sync(qmask, s, 2);
                        float y = s * 0.125f;
                        if (!(j == i || j == i - 1)) y = y * -1000000000.0f;
                        const float* vg = &g_v[(size_t)j * DMODEL + hb + t4 * 16];
                        if ((e & 3) < 2) {
                            if (y > rmax0) {
                                float scl = expf(rmax0 - y);
                                rsum0 *= scl;
#pragma unroll
                                for (int d = 0; d < 16; d++) acc0[d] *= scl;
                                rmax0 = y;
                            }
                            float p = expf(y - rmax0);
                            rsum0 += p;
#pragma unroll
                            for (int c4 = 0; c4 < 4; c4++) {
                                float4 vv = *(const float4*)&vg[c4 * 4];
                                acc0[c4 * 4 + 0] = fmaf(p, vv.x, acc0[c4 * 4 + 0]);
                                acc0[c4 * 4 + 1] = fmaf(p, vv.y, acc0[c4 * 4 + 1]);
                                acc0[c4 * 4 + 2] = fmaf(p, vv.z, acc0[c4 * 4 + 2]);
                                acc0[c4 * 4 + 3] = fmaf(p, vv.w, acc0[c4 * 4 + 3]);
                            }
                        } else {
                            if (y > rmax1) {
                                float scl = expf(rmax1 - y);
                                rsum1 *= scl;
#pragma unroll
                                for (int d = 0; d < 16; d++) acc1[d] *= scl;
                                rmax1 = y;
                            }
                            float p = expf(y - rmax1);
                            rsum1 += p;
#pragma unroll
                            for (int c4 = 0; c4 < 4; c4++) {
                                float4 vv = *(const float4*)&vg[c4 * 4];
                                acc1[c4 * 4 + 0] = fmaf(p, vv.x, acc1[c4 * 4 + 0]);
                                acc1[c4 * 4 + 1] = fmaf(p, vv.y, acc1[c4 * 4 + 1]);
                                acc1[c4 * 4 + 2] = fmaf(p, vv.z, acc1[c4 * 4 + 2]);
                                acc1[c4 * 4 + 3] = fmaf(p, vv.w, acc1[c4 * 4 + 3]);
                            }
                        }
                    }
                }
            }
        }
        run0 = fminf(run0, __shfl_xor_sync(0xffffffffu, run0, 1));
        run0 = fminf(run0, __shfl_xor_sync(0xffffffffu, run0, 2));
        run1 = fminf(run1, __shfl_xor_sync(0xffffffffu, run1, 1));
        run1 = fminf(run1, __shfl_xor_sync(0xffffffffu, run1, 2));
    }

    {
        float inv0 = 1.f / rsum0;
        float inv1 = 1.f / rsum1;
        float* o0 = &g_attn[(size_t)R0 * DMODEL + hb + t4 * 16];
        float* o1 = &g_attn[(size_t)R1 * DMODEL + hb + t4 * 16];
#pragma unroll
        for (int c4 = 0; c4 < 4; c4++) {
            float4 a = {acc0[c4 * 4 + 0] * inv0, acc0[c4 * 4 + 1] * inv0,
                        acc0[c4 * 4 + 2] * inv0, acc0[c4 * 4 + 3] * inv0};
            float4 b = {acc1[c4 * 4 + 0] * inv1, acc1[c4 * 4 + 1] * inv1,
                        acc1[c4 * 4 + 2] * inv1, acc1[c4 * 4 + 3] * inv1};
            *(float4*)&o0[c4 * 4] = a;
            *(float4*)&o1[c4 * 4] = b;
        }
    }
}

// ---------------------------------------------------------------------------
// K3: out[4096,64] = g_attn[4096,1024] @ Wm[1024,64] + bm  (verbatim)
// ---------------------------------------------------------------------------
__global__ __launch_bounds__(256) void sgemm_out(
    const float* __restrict__ A, const float* __restrict__ B,
    const float* __restrict__ bias, float* __restrict__ C)
{
    __shared__ float As[16][64];
    __shared__ float Bs[16][64];

    const int tid = threadIdx.x;
    const int tx = tid & 15, ty = tid >> 4;
    const int by = blockIdx.x * 64;

    const int ar = tid >> 2;
    const int ac = (tid & 3) * 4;
    const int br = tid >> 4;
    const int bc = (tid & 15) * 4;

    float acc[4][4];
#pragma unroll
    for (int i = 0; i < 4; i++)
#pragma unroll
        for (int j = 0; j < 4; j++) acc[i][j] = 0.f;

    for (int k0 = 0; k0 < DMODEL; k0 += 16) {
        float4 av = *(const float4*)&A[(size_t)(by + ar) * DMODEL + k0 + ac];
        float4 bv = *(const float4*)&B[(size_t)(k0 + br) * 64 + bc];
        As[ac + 0][ar] = av.x;
        As[ac + 1][ar] = av.y;
        As[ac + 2][ar] = av.z;
        As[ac + 3][ar] = av.w;
        *(float4*)&Bs[br][bc] = bv;
        __syncthreads();
#pragma unroll
        for (int kk = 0; kk < 16; kk++) {
            float4 a = *(const float4*)&As[kk][ty * 4];
            float4 b = *(const float4*)&Bs[kk][tx * 4];
            float av4[4] = {a.x, a.y, a.z, a.w};
            float bv4[4] = {b.x, b.y, b.z, b.w};
#pragma unroll
            for (int i = 0; i < 4; i++)
#pragma unroll
                for (int j = 0; j < 4; j++)
                    acc[i][j] = fmaf(av4[i], bv4[j], acc[i][j]);
        }
        __syncthreads();
    }

#pragma unroll
    for (int i = 0; i < 4; i++) {
        int row = by + ty * 4 + i;
        float4 o;
        o.x = acc[i][0] + bias[tx * 4 + 0];
        o.y = acc[i][1] + bias[tx * 4 + 1];
        o.z = acc[i][2] + bias[tx * 4 + 2];
        o.w = acc[i][3] + bias[tx * 4 + 3];
        *(float4*)&C[(size_t)row * 64 + tx * 4] = o;
    }
}

// ---------------------------------------------------------------------------
// kernel_launch
// ---------------------------------------------------------------------------
extern "C" void kernel_launch(void* const* d_in, const int* in_sizes, int n_in,
                              void* d_out, int out_size)
{
    const float* X  = (const float*)d_in[0];
    const float* Wq = (const float*)d_in[2];
    const float* bq = (const float*)d_in[3];
    const float* Wk = (const float*)d_in[4];
    const float* bk = (const float*)d_in[5];
    const float* Wv = (const float*)d_in[6];
    const float* bv = (const float*)d_in[7];
    const float* Wm = (const float*)d_in[8];
    const float* bm = (const float*)d_in[9];
    float* out = (float*)d_out;

    float *qp, *kp, *vp, *ap;
    cudaGetSymbolAddress((void**)&qp, g_q);
    cudaGetSymbolAddress((void**)&kp, g_k);
    cudaGetSymbolAddress((void**)&vp, g_v);
    cudaGetSymbolAddress((void**)&ap, g_attn);

    cudaFuncSetAttribute(sgemm_qkv,
                         cudaFuncAttributeMaxDynamicSharedMemorySize,
                         QKV_SMEM_BYTES);
    sgemm_qkv<<<dim3(24, 32), 256, QKV_SMEM_BYTES>>>(
        X, Wq, Wk, Wv, bq, bk, bv, qp, kp, vp);

    cudaFuncSetAttribute(attn_kernel,
                         cudaFuncAttributeMaxDynamicSharedMemorySize,
                         ATT_SMEM_BYTES);
    attn_kernel<<<dim3(SQ / 128, NH), 256, ATT_SMEM_BYTES>>>();

    sgemm_out<<<SQ / 64, 256>>>(ap, Wm, bm, out);
}